// round 1
// baseline (speedup 1.0000x reference)
#include <cuda_runtime.h>
#include <math.h>

// Problem constants
#define N_RAYS    65536
#define N_SAMPLES 192
#define NGROUPS   6        // 192 / 32
#define EPSV      1e-10f

// Output layout: flattened tuple concat
//   rgb_map  : [N,3]    offset 0
//   density  : [N,191]  offset N*3
//   acc_map  : [N]      offset N*194
//   weights  : [N,192]  offset N*195
//   depth    : [N]      offset N*387
#define OFF_RGB   0
#define OFF_DENS  (N_RAYS * 3)
#define OFF_ACC   (N_RAYS * 194)
#define OFF_W     (N_RAYS * 195)
#define OFF_DEPTH (N_RAYS * 387)

__global__ __launch_bounds__(256)
void nerf_volrender_kernel(const float4* __restrict__ raw4,
                           const float*  __restrict__ z_vals,
                           const float*  __restrict__ rays_d,
                           float*        __restrict__ out)
{
    const unsigned FULL = 0xFFFFFFFFu;
    int gwarp = (blockIdx.x * blockDim.x + threadIdx.x) >> 5;
    int lane  = threadIdx.x & 31;
    if (gwarp >= N_RAYS) return;
    const int r = gwarp;

    // --- ray direction norm (uniform-address loads: single broadcast request) ---
    float dx = __ldg(&rays_d[r * 3 + 0]);
    float dy = __ldg(&rays_d[r * 3 + 1]);
    float dz = __ldg(&rays_d[r * 3 + 2]);
    float dnorm = sqrtf(dx * dx + dy * dy + dz * dz);

    // --- coalesced loads: sample s = 32*j + lane ---
    float  zv[NGROUPS];
    float4 rv[NGROUPS];
    const int zbase = r * N_SAMPLES;
    #pragma unroll
    for (int j = 0; j < NGROUPS; j++) {
        int s = (j << 5) + lane;
        zv[j] = __ldg(&z_vals[zbase + s]);
        rv[j] = __ldg(&raw4[zbase + s]);
    }

    float runprod = 1.0f;           // product of all t terms in groups < j
    float sr = 0.f, sg = 0.f, sb = 0.f, sw = 0.f, sd = 0.f;

    #pragma unroll
    for (int j = 0; j < NGROUPS; j++) {
        const int s = (j << 5) + lane;

        // z[s+1]: shuffle within group; lane 31 takes next group's lane 0
        float zn = __shfl_down_sync(FULL, zv[j], 1);
        if (j < NGROUPS - 1) {
            float znext0 = __shfl_sync(FULL, zv[j + 1], 0);
            if (lane == 31) zn = znext0;
        }
        float dist = fabsf(zn - zv[j]) * dnorm;

        float dens = fmaxf(rv[j].w, 0.0f);
        bool  last = (s == N_SAMPLES - 1);

        float alpha = last ? 1.0f : (1.0f - __expf(-dens * dist));

        // density output only for s < 191
        if (s < N_SAMPLES - 1)
            out[OFF_DENS + r * (N_SAMPLES - 1) + s] = dens;

        // multiplicative inclusive scan of t = (1+eps) - alpha within this group
        float t = (1.0f + EPSV) - alpha;
        float p = t;
        #pragma unroll
        for (int d = 1; d < 32; d <<= 1) {
            float o = __shfl_up_sync(FULL, p, d);
            if (lane >= d) p *= o;
        }
        // exclusive scan value
        float excl = __shfl_up_sync(FULL, p, 1);
        if (lane == 0) excl = 1.0f;

        float trans = runprod * excl;       // prod of all t[k], k < s
        float w = alpha * trans;

        out[OFF_W + r * N_SAMPLES + s] = w;

        // rgb sigmoid + weighted accumulation
        float rr = 1.0f / (1.0f + __expf(-rv[j].x));
        float gg = 1.0f / (1.0f + __expf(-rv[j].y));
        float bb = 1.0f / (1.0f + __expf(-rv[j].z));
        sr += w * rr;
        sg += w * gg;
        sb += w * bb;
        sw += w;
        sd += w * zv[j];

        // carry full-group product forward
        runprod *= __shfl_sync(FULL, p, 31);
    }

    // --- warp reduction of the 5 accumulators ---
    #pragma unroll
    for (int d = 16; d > 0; d >>= 1) {
        sr += __shfl_down_sync(FULL, sr, d);
        sg += __shfl_down_sync(FULL, sg, d);
        sb += __shfl_down_sync(FULL, sb, d);
        sw += __shfl_down_sync(FULL, sw, d);
        sd += __shfl_down_sync(FULL, sd, d);
    }
    if (lane == 0) {
        out[OFF_RGB + r * 3 + 0] = sr;
        out[OFF_RGB + r * 3 + 1] = sg;
        out[OFF_RGB + r * 3 + 2] = sb;
        out[OFF_ACC   + r] = sw;
        out[OFF_DEPTH + r] = sd;
    }
}

extern "C" void kernel_launch(void* const* d_in, const int* in_sizes, int n_in,
                              void* d_out, int out_size)
{
    const float4* raw4   = (const float4*)d_in[0];   // [N, S, 4] f32
    const float*  z_vals = (const float*)d_in[1];    // [N, S]    f32
    const float*  rays_d = (const float*)d_in[2];    // [N, 3]    f32
    float* out = (float*)d_out;

    // one warp per ray: 65536 warps, 8 warps/block -> 8192 blocks
    const int threads = 256;
    const int blocks  = (N_RAYS * 32) / threads;
    nerf_volrender_kernel<<<blocks, threads>>>(raw4, z_vals, rays_d, out);
}

// round 2
// speedup vs baseline: 1.1871x; 1.1871x over previous
#include <cuda_runtime.h>
#include <math.h>

#define N_RAYS    65536
#define N_SAMPLES 192
#define NGROUPS   6
#define EPSV      1e-10f

// Output layout: flattened tuple concat
#define OFF_RGB   0
#define OFF_DENS  (N_RAYS * 3)
#define OFF_ACC   (N_RAYS * 194)
#define OFF_W     (N_RAYS * 195)
#define OFF_DEPTH (N_RAYS * 387)

__device__ __forceinline__ float fast_sigmoid(float x) {
    float t;
    asm("tanh.approx.f32 %0, %1;" : "=f"(t) : "f"(x * 0.5f));
    return fmaf(t, 0.5f, 0.5f);
}

__global__ __launch_bounds__(256, 5)
void nerf_volrender_kernel(const float4* __restrict__ raw4,
                           const float*  __restrict__ z_vals,
                           const float*  __restrict__ rays_d,
                           float*        __restrict__ out)
{
    const unsigned FULL = 0xFFFFFFFFu;
    int gwarp = (blockIdx.x * blockDim.x + threadIdx.x) >> 5;
    int lane  = threadIdx.x & 31;
    if (gwarp >= N_RAYS) return;
    const int r = gwarp;

    float dx = __ldg(&rays_d[r * 3 + 0]);
    float dy = __ldg(&rays_d[r * 3 + 1]);
    float dz = __ldg(&rays_d[r * 3 + 2]);
    float dnorm = sqrtf(dx * dx + dy * dy + dz * dz);

    // coalesced streaming loads: sample s = 32*j + lane
    float  zv[NGROUPS];
    float4 rv[NGROUPS];
    const int zbase = r * N_SAMPLES;
    #pragma unroll
    for (int j = 0; j < NGROUPS; j++) {
        int s = (j << 5) + lane;
        zv[j] = __ldcs(&z_vals[zbase + s]);
        rv[j] = __ldcs(&raw4[zbase + s]);
    }

    // ---- phase 1: per-group independent scans (ILP across groups) ----
    float p[NGROUPS];   // inclusive product of t within group
    #pragma unroll
    for (int j = 0; j < NGROUPS; j++) {
        const int s = (j << 5) + lane;

        // z[s+1]: shuffle within group; lane 31 takes next group's lane 0
        float zn = __shfl_down_sync(FULL, zv[j], 1);
        if (j < NGROUPS - 1) {
            float znext0 = __shfl_sync(FULL, zv[j + 1], 0);
            if (lane == 31) zn = znext0;
        }
        float dist = fabsf(zn - zv[j]) * dnorm;

        float dens = fmaxf(rv[j].w, 0.0f);
        if (s < N_SAMPLES - 1)
            __stcs(&out[OFF_DENS + r * (N_SAMPLES - 1) + s], dens);

        bool last = (s == N_SAMPLES - 1);
        float alpha = last ? 1.0f : (1.0f - __expf(-dens * dist));
        float t = (1.0f + EPSV) - alpha;

        // multiplicative inclusive warp scan of t
        float pp = t;
        #pragma unroll
        for (int d = 1; d < 32; d <<= 1) {
            float o = __shfl_up_sync(FULL, pp, d);
            if (lane >= d) pp *= o;
        }
        p[j] = pp;
    }

    // ---- phase 2: combine groups; w = (1+eps)*trans - incl (exact) ----
    float off = 1.0f;
    float sr = 0.f, sg = 0.f, sb = 0.f, sw = 0.f, sd = 0.f;
    #pragma unroll
    for (int j = 0; j < NGROUPS; j++) {
        const int s = (j << 5) + lane;

        float excl = __shfl_up_sync(FULL, p[j], 1);
        if (lane == 0) excl = 1.0f;
        float trans = off * excl;           // exclusive cumprod up to sample s
        float incl  = off * p[j];           // inclusive cumprod (= trans * t)
        float w = fmaf(EPSV, trans, trans - incl);   // alpha*trans, exactly

        __stcs(&out[OFF_W + r * N_SAMPLES + s], w);

        float rr = fast_sigmoid(rv[j].x);
        float gg = fast_sigmoid(rv[j].y);
        float bb = fast_sigmoid(rv[j].z);
        sr += w * rr;
        sg += w * gg;
        sb += w * bb;
        sw += w;
        sd += w * zv[j];

        off *= __shfl_sync(FULL, p[j], 31);
    }

    // ---- warp reduction of the 5 accumulators ----
    #pragma unroll
    for (int d = 16; d > 0; d >>= 1) {
        sr += __shfl_down_sync(FULL, sr, d);
        sg += __shfl_down_sync(FULL, sg, d);
        sb += __shfl_down_sync(FULL, sb, d);
        sw += __shfl_down_sync(FULL, sw, d);
        sd += __shfl_down_sync(FULL, sd, d);
    }
    if (lane == 0) {
        out[OFF_RGB + r * 3 + 0] = sr;
        out[OFF_RGB + r * 3 + 1] = sg;
        out[OFF_RGB + r * 3 + 2] = sb;
        out[OFF_ACC   + r] = sw;
        out[OFF_DEPTH + r] = sd;
    }
}

extern "C" void kernel_launch(void* const* d_in, const int* in_sizes, int n_in,
                              void* d_out, int out_size)
{
    const float4* raw4   = (const float4*)d_in[0];
    const float*  z_vals = (const float*)d_in[1];
    const float*  rays_d = (const float*)d_in[2];
    float* out = (float*)d_out;

    const int threads = 256;
    const int blocks  = (N_RAYS * 32) / threads;
    nerf_volrender_kernel<<<blocks, threads>>>(raw4, z_vals, rays_d, out);
}